// round 1
// baseline (speedup 1.0000x reference)
#include <cuda_runtime.h>

#define BATCH 8
#define SEQ   2048
#define DIM   512

// Scratch (allocation-free rule: __device__ globals)
__device__ float g_sq[(size_t)BATCH * SEQ * DIM];  // sigmoid(q)
__device__ float g_kw[(size_t)BATCH * SEQ * DIM];  // exp(k)
__device__ float g_kv[(size_t)BATCH * SEQ * DIM];  // exp(k)*v

typedef unsigned long long u64;

__device__ __forceinline__ u64 pack_dup(float a) {
    u64 r; asm("mov.b64 %0, {%1, %1};" : "=l"(r) : "f"(a)); return r;
}
__device__ __forceinline__ u64 pack2(float lo, float hi) {
    u64 r; asm("mov.b64 %0, {%1, %2};" : "=l"(r) : "f"(lo), "f"(hi)); return r;
}
__device__ __forceinline__ float2 unpack2(u64 v) {
    float2 r; asm("mov.b64 {%0, %1}, %2;" : "=f"(r.x), "=f"(r.y) : "l"(v)); return r;
}
// Packed dual-FMA: 2 fp32 MACs per instruction (Blackwell f32x2 pipe)
__device__ __forceinline__ void fma2(u64& d, u64 a, u64 b) {
    asm("fma.rn.f32x2 %0, %1, %2, %0;" : "+l"(d) : "l"(a), "l"(b));
}

// ============================================================================
// Kernel 1: fused QKV projection + nonlinear epilogue.
//   q,k,v[m,n] = sum_k x[m,k] * W{q,k,v}[n,k]   (x: [16384,512], W: [512,512])
//   g_sq = sigmoid(q); g_kw = exp(k); g_kv = exp(k)*v
// Tile 128(m) x 64(n), BK=16, 256 threads, per-thread 8m x 4n x 3 mats.
// ============================================================================
__global__ __launch_bounds__(256, 1)
void qkv_kernel(const float* __restrict__ x,
                const float* __restrict__ Wq,
                const float* __restrict__ Wk,
                const float* __restrict__ Wv)
{
    const int BM = 128, BN = 64, BK = 16;
    __shared__ float xs[BK][BM + 4];     // x tile, transposed [k][m]
    __shared__ float ws[3][BK][BN];      // weight tiles, transposed [k][n]

    const int tid = threadIdx.x;
    const int tx  = tid & 15;            // n direction (4 cols each)
    const int ty  = tid >> 4;            // m direction (8 rows each)
    const int m0  = blockIdx.y * BM;
    const int n0  = blockIdx.x * BN;

    u64 acc[3][8][2];
    #pragma unroll
    for (int a = 0; a < 3; a++)
        #pragma unroll
        for (int i = 0; i < 8; i++) { acc[a][i][0] = 0ULL; acc[a][i][1] = 0ULL; }

    const float* Wmats[3] = {Wq, Wk, Wv};

    for (int k0 = 0; k0 < DIM; k0 += BK) {
        // x tile: 128x16, float4 loads along k, scalar transposed stores
        #pragma unroll
        for (int r = 0; r < 2; r++) {
            int f  = tid + r * 256;        // 0..511
            int m  = f >> 2;               // 0..127
            int kq = (f & 3) << 2;         // 0,4,8,12
            float4 v = *(const float4*)(x + (size_t)(m0 + m) * DIM + k0 + kq);
            xs[kq + 0][m] = v.x; xs[kq + 1][m] = v.y;
            xs[kq + 2][m] = v.z; xs[kq + 3][m] = v.w;
        }
        // W tiles: 64x16 each
        {
            int n  = tid >> 2;             // 0..63
            int kq = (tid & 3) << 2;
            #pragma unroll
            for (int mat = 0; mat < 3; mat++) {
                float4 v = *(const float4*)(Wmats[mat] + (size_t)(n0 + n) * DIM + k0 + kq);
                ws[mat][kq + 0][n] = v.x; ws[mat][kq + 1][n] = v.y;
                ws[mat][kq + 2][n] = v.z; ws[mat][kq + 3][n] = v.w;
            }
        }
        __syncthreads();

        #pragma unroll
        for (int kk = 0; kk < BK; kk++) {
            float4 a0 = *(const float4*)&xs[kk][ty * 8];
            float4 a1 = *(const float4*)&xs[kk][ty * 8 + 4];
            u64 a2[8];
            a2[0] = pack_dup(a0.x); a2[1] = pack_dup(a0.y);
            a2[2] = pack_dup(a0.z); a2[3] = pack_dup(a0.w);
            a2[4] = pack_dup(a1.x); a2[5] = pack_dup(a1.y);
            a2[6] = pack_dup(a1.z); a2[7] = pack_dup(a1.w);
            #pragma unroll
            for (int mat = 0; mat < 3; mat++) {
                float4 bv = *(const float4*)&ws[mat][kk][tx * 4];
                u64 b2lo = pack2(bv.x, bv.y);
                u64 b2hi = pack2(bv.z, bv.w);
                #pragma unroll
                for (int i = 0; i < 8; i++) {
                    fma2(acc[mat][i][0], a2[i], b2lo);
                    fma2(acc[mat][i][1], a2[i], b2hi);
                }
            }
        }
        __syncthreads();
    }

    // Epilogue: nonlinearities, write scratch
    #pragma unroll
    for (int i = 0; i < 8; i++) {
        int m = m0 + ty * 8 + i;
        size_t base = (size_t)m * DIM;
        #pragma unroll
        for (int p = 0; p < 2; p++) {
            int n = n0 + tx * 4 + p * 2;
            float2 q = unpack2(acc[0][i][p]);
            float2 k = unpack2(acc[1][i][p]);
            float2 v = unpack2(acc[2][i][p]);
            float2 sq, kw, kv;
            sq.x = 1.0f / (1.0f + __expf(-q.x));
            sq.y = 1.0f / (1.0f + __expf(-q.y));
            kw.x = __expf(k.x); kw.y = __expf(k.y);
            kv.x = kw.x * v.x;  kv.y = kw.y * v.y;
            *(float2*)(g_sq + base + n) = sq;
            *(float2*)(g_kw + base + n) = kw;
            *(float2*)(g_kv + base + n) = kv;
        }
    }
}

// ============================================================================
// Kernel 2: fused dual aggregation GEMM + ratio epilogue.
//   dw[i,j] = exp(-alpha*11*dis[b,i,j])          (computed on the fly)
//   w1[j,d] = sum_i dw[i,j]*g_kv[b,i,d]
//   w2[j,d] = sum_i dw[i,j]*g_kw[b,i,d]
//   out[b,j,d] = g_sq[b,j,d] * w1/w2
// Tile 128(j) x 64(d), BK=16, 256 threads, per-thread 8j x 4d x 2 outputs.
// dw tile is loaded ONCE and feeds both GEMMs (halves dis traffic, doubles
// MAC/smem-byte to the 1.0 balance point).
// ============================================================================
__global__ __launch_bounds__(256, 2)
void agg_kernel(const float* __restrict__ dis,
                const float* __restrict__ alpha_p,
                float* __restrict__ out)
{
    const int BJ = 128, BD = 64, BK = 16;
    __shared__ float dws[BK][BJ];
    __shared__ float kvs[BK][BD];
    __shared__ float kws[BK][BD];

    const int tid = threadIdx.x;
    const int tx  = tid & 15;            // d direction (4 each)
    const int ty  = tid >> 4;            // j direction (8 each)
    const int b   = blockIdx.z;
    const int j0  = blockIdx.y * BJ;
    const int d0  = blockIdx.x * BD;
    const float c = -alpha_p[0] * 11.0f; // -alpha * log2(2048)

    u64 acc1[8][2], acc2[8][2];
    #pragma unroll
    for (int i = 0; i < 8; i++) {
        acc1[i][0] = 0ULL; acc1[i][1] = 0ULL;
        acc2[i][0] = 0ULL; acc2[i][1] = 0ULL;
    }

    const float* disb = dis  + (size_t)b * SEQ * SEQ;
    const float* kvb  = g_kv + (size_t)b * SEQ * DIM;
    const float* kwb  = g_kw + (size_t)b * SEQ * DIM;

    for (int i0 = 0; i0 < SEQ; i0 += BK) {
        // dis tile 16x128, exp applied on load
        #pragma unroll
        for (int r = 0; r < 2; r++) {
            int f  = tid + r * 256;        // 0..511
            int i  = f >> 5;               // 0..15
            int jq = (f & 31) << 2;        // 0..124
            float4 v = *(const float4*)(disb + (size_t)(i0 + i) * SEQ + j0 + jq);
            float4 e;
            e.x = __expf(c * v.x); e.y = __expf(c * v.y);
            e.z = __expf(c * v.z); e.w = __expf(c * v.w);
            *(float4*)&dws[i][jq] = e;
        }
        // kv / kw tiles 16x64
        {
            int i  = tid >> 4;             // 0..15
            int dq = (tid & 15) << 2;      // 0..60
            *(float4*)&kvs[i][dq] = *(const float4*)(kvb + (size_t)(i0 + i) * DIM + d0 + dq);
            *(float4*)&kws[i][dq] = *(const float4*)(kwb + (size_t)(i0 + i) * DIM + d0 + dq);
        }
        __syncthreads();

        #pragma unroll
        for (int kk = 0; kk < BK; kk++) {
            float4 a0 = *(const float4*)&dws[kk][ty * 8];
            float4 a1 = *(const float4*)&dws[kk][ty * 8 + 4];
            u64 a2[8];
            a2[0] = pack_dup(a0.x); a2[1] = pack_dup(a0.y);
            a2[2] = pack_dup(a0.z); a2[3] = pack_dup(a0.w);
            a2[4] = pack_dup(a1.x); a2[5] = pack_dup(a1.y);
            a2[6] = pack_dup(a1.z); a2[7] = pack_dup(a1.w);
            float4 b1 = *(const float4*)&kvs[kk][tx * 4];
            float4 b2 = *(const float4*)&kws[kk][tx * 4];
            u64 b1lo = pack2(b1.x, b1.y), b1hi = pack2(b1.z, b1.w);
            u64 b2lo = pack2(b2.x, b2.y), b2hi = pack2(b2.z, b2.w);
            #pragma unroll
            for (int i = 0; i < 8; i++) {
                fma2(acc1[i][0], a2[i], b1lo);
                fma2(acc1[i][1], a2[i], b1hi);
                fma2(acc2[i][0], a2[i], b2lo);
                fma2(acc2[i][1], a2[i], b2hi);
            }
        }
        __syncthreads();
    }

    // Epilogue: out = sigmoid(q) * w1/w2
    const float* sqb  = g_sq + (size_t)b * SEQ * DIM;
    float*       outb = out  + (size_t)b * SEQ * DIM;
    #pragma unroll
    for (int i = 0; i < 8; i++) {
        int j = j0 + ty * 8 + i;
        size_t base = (size_t)j * DIM;
        #pragma unroll
        for (int p = 0; p < 2; p++) {
            int d = d0 + tx * 4 + p * 2;
            float2 w1 = unpack2(acc1[i][p]);
            float2 w2 = unpack2(acc2[i][p]);
            float2 s  = *(const float2*)(sqb + base + d);
            float2 o;
            o.x = s.x * __fdividef(w1.x, w2.x);
            o.y = s.y * __fdividef(w1.y, w2.y);
            *(float2*)(outb + base + d) = o;
        }
    }
}

extern "C" void kernel_launch(void* const* d_in, const int* in_sizes, int n_in,
                              void* d_out, int out_size)
{
    const float* x     = (const float*)d_in[0];   // [8,2048,512]
    const float* dis   = (const float*)d_in[1];   // [8,2048,2048]
    const float* Wq    = (const float*)d_in[2];   // [512,512]
    const float* Wk    = (const float*)d_in[3];
    const float* Wv    = (const float*)d_in[4];
    const float* alpha = (const float*)d_in[5];   // scalar
    float* out = (float*)d_out;                   // [8,2048,512]

    dim3 g1(DIM / 64, (BATCH * SEQ) / 128);       // (8, 128)
    qkv_kernel<<<g1, 256>>>(x, Wq, Wk, Wv);

    dim3 g2(DIM / 64, SEQ / 128, BATCH);          // (8, 16, 8)
    agg_kernel<<<g2, 256>>>(dis, alpha, out);
}

// round 4
// speedup vs baseline: 1.1016x; 1.1016x over previous
#include <cuda_runtime.h>
#include <mma.h>
#include <cstdint>

using namespace nvcuda;

#define BATCH 8
#define SEQ   2048
#define DIM   512

// Scratch (__device__ globals per allocation-free rule)
__device__ float g_sq[(size_t)BATCH * SEQ * DIM];  // sigmoid(q)      [b][i][d]
__device__ float g_kw[(size_t)BATCH * SEQ * DIM];  // exp(k) (tf32)   [b][i][d]
__device__ float g_kv[(size_t)BATCH * SEQ * DIM];  // exp(k)*v (tf32) [b][i][d]

typedef unsigned long long u64;

// ---------------------------------------------------------------- helpers ---
__device__ __forceinline__ u64 pack_dup(float a) {
    u64 r; asm("mov.b64 %0, {%1, %1};" : "=l"(r) : "f"(a)); return r;
}
__device__ __forceinline__ u64 pack2(float lo, float hi) {
    u64 r; asm("mov.b64 %0, {%1, %2};" : "=l"(r) : "f"(lo), "f"(hi)); return r;
}
__device__ __forceinline__ float2 unpack2(u64 v) {
    float2 r; asm("mov.b64 {%0, %1}, %2;" : "=f"(r.x), "=f"(r.y) : "l"(v)); return r;
}
__device__ __forceinline__ void fma2(u64& d, u64 a, u64 b) {
    asm("fma.rn.f32x2 %0, %1, %2, %0;" : "+l"(d) : "l"(a), "l"(b));
}
// Unbiased round-to-nearest tf32 (value stays fp32-representable; later HW
// truncation to tf32 inside HMMA is then exact).
__device__ __forceinline__ float to_tf32(float x) {
    uint32_t u; asm("cvt.rna.tf32.f32 %0, %1;" : "=r"(u) : "f"(x));
    return __uint_as_float(u);
}

// ============================================================================
// Kernel 1: fused QKV projection + nonlinear epilogue (fp32 SIMT, f32x2 FMA).
// PROVEN in R1 — only change vs R1: kw/kv stores are tf32-pre-rounded.
// ============================================================================
__global__ __launch_bounds__(256, 1)
void qkv_kernel(const float* __restrict__ x,
                const float* __restrict__ Wq,
                const float* __restrict__ Wk,
                const float* __restrict__ Wv)
{
    const int BK = 16;
    __shared__ float xs[BK][132];
    __shared__ float ws[3][BK][64];

    const int tid = threadIdx.x;
    const int tx  = tid & 15;
    const int ty  = tid >> 4;
    const int m0  = blockIdx.y * 128;
    const int n0  = blockIdx.x * 64;

    u64 acc[3][8][2];
    #pragma unroll
    for (int a = 0; a < 3; a++)
        #pragma unroll
        for (int i = 0; i < 8; i++) { acc[a][i][0] = 0ULL; acc[a][i][1] = 0ULL; }

    const float* Wmats[3] = {Wq, Wk, Wv};

    for (int k0 = 0; k0 < DIM; k0 += BK) {
        #pragma unroll
        for (int r = 0; r < 2; r++) {
            int f  = tid + r * 256;
            int m  = f >> 2;
            int kq = (f & 3) << 2;
            float4 v = *(const float4*)(x + (size_t)(m0 + m) * DIM + k0 + kq);
            xs[kq + 0][m] = v.x; xs[kq + 1][m] = v.y;
            xs[kq + 2][m] = v.z; xs[kq + 3][m] = v.w;
        }
        {
            int n  = tid >> 2;
            int kq = (tid & 3) << 2;
            #pragma unroll
            for (int mat = 0; mat < 3; mat++) {
                float4 v = *(const float4*)(Wmats[mat] + (size_t)(n0 + n) * DIM + k0 + kq);
                ws[mat][kq + 0][n] = v.x; ws[mat][kq + 1][n] = v.y;
                ws[mat][kq + 2][n] = v.z; ws[mat][kq + 3][n] = v.w;
            }
        }
        __syncthreads();

        #pragma unroll
        for (int kk = 0; kk < BK; kk++) {
            float4 a0 = *(const float4*)&xs[kk][ty * 8];
            float4 a1 = *(const float4*)&xs[kk][ty * 8 + 4];
            u64 a2[8];
            a2[0] = pack_dup(a0.x); a2[1] = pack_dup(a0.y);
            a2[2] = pack_dup(a0.z); a2[3] = pack_dup(a0.w);
            a2[4] = pack_dup(a1.x); a2[5] = pack_dup(a1.y);
            a2[6] = pack_dup(a1.z); a2[7] = pack_dup(a1.w);
            #pragma unroll
            for (int mat = 0; mat < 3; mat++) {
                float4 bv = *(const float4*)&ws[mat][kk][tx * 4];
                u64 b2lo = pack2(bv.x, bv.y);
                u64 b2hi = pack2(bv.z, bv.w);
                #pragma unroll
                for (int i = 0; i < 8; i++) {
                    fma2(acc[mat][i][0], a2[i], b2lo);
                    fma2(acc[mat][i][1], a2[i], b2hi);
                }
            }
        }
        __syncthreads();
    }

    #pragma unroll
    for (int i = 0; i < 8; i++) {
        int m = m0 + ty * 8 + i;
        size_t base = (size_t)m * DIM;
        #pragma unroll
        for (int p = 0; p < 2; p++) {
            int n = n0 + tx * 4 + p * 2;
            float2 q = unpack2(acc[0][i][p]);
            float2 k = unpack2(acc[1][i][p]);
            float2 v = unpack2(acc[2][i][p]);
            float2 sq, kw, kv;
            sq.x = 1.0f / (1.0f + __expf(-q.x));
            sq.y = 1.0f / (1.0f + __expf(-q.y));
            kw.x = __expf(k.x); kw.y = __expf(k.y);
            kv.x = to_tf32(kw.x * v.x); kv.y = to_tf32(kw.y * v.y);
            kw.x = to_tf32(kw.x);       kw.y = to_tf32(kw.y);
            *(float2*)(g_sq + base + n) = sq;
            *(float2*)(g_kw + base + n) = kw;
            *(float2*)(g_kv + base + n) = kv;
        }
    }
}

// ============================================================================
// Kernel 2: WMMA tf32 dual aggregation GEMM (legacy mma.sync — portable PTX).
//   C1[d,j] = sum_i kv[i,d]*dw[i,j],  C2 likewise with kw.  BK=16.
//   A = g_kv/g_kw natural [i][d] layout as wmma col_major  (no transpose!)
//   B = exp(c*dis[i][j]) natural row_major, shared by both GEMMs.
//   Tile 128(d) x 128(j), 512 threads = 4x4 warps, 32x32x2 per warp.
//   K loop: 128 chunks of 16 i  (R3 bug: only 64 -> half the contraction).
//   Epilogue: ratio in-fragment, store mem_col_major -> smem [j][d], then
//   coalesced sq * ratio writes.
// ============================================================================
#define NCHUNK 128          // SEQ / 16
#define STG 6336            // floats per stage: 3 tiles of 16x132
#define AGG_SMEM_BYTES (128 * 132 * 4)   // 67584 >= 2*STG*4 (50688)

__global__ __launch_bounds__(512, 1)
void agg_wmma(const float* __restrict__ dis,
              const float* __restrict__ alpha_p,
              float* __restrict__ out)
{
    extern __shared__ float smem[];

    const int tid = threadIdx.x;
    const int wid = tid >> 5;
    const int b   = blockIdx.z;
    const int j0  = blockIdx.y * 128;
    const int d0  = blockIdx.x * 128;
    const float c = -alpha_p[0] * 11.0f;   // -alpha * log2(2048)

    const int wm = wid & 3, wn = wid >> 2;
    const int msub = wm * 32, nsub = wn * 32;

    wmma::fragment<wmma::accumulator, 16, 16, 8, float> acc1[2][2], acc2[2][2];
    #pragma unroll
    for (int mt = 0; mt < 2; mt++)
        #pragma unroll
        for (int nt = 0; nt < 2; nt++) {
            wmma::fill_fragment(acc1[mt][nt], 0.0f);
            wmma::fill_fragment(acc2[mt][nt], 0.0f);
        }

    const float* kvb  = g_kv + (size_t)b * SEQ * DIM;
    const float* kwb  = g_kw + (size_t)b * SEQ * DIM;
    const float* disb = dis  + (size_t)b * SEQ * SEQ;

    const int ia = tid >> 5;          // 0..15 (i within chunk)
    const int c4 = (tid & 31) << 2;   // 0..124 (col within tile)

    float4 v1, v2, v3;
    // preload + store chunk 0
    {
        v1 = *(const float4*)(kvb  + (size_t)ia * DIM + d0 + c4);
        v2 = *(const float4*)(kwb  + (size_t)ia * DIM + d0 + c4);
        v3 = *(const float4*)(disb + (size_t)ia * SEQ + j0 + c4);
        float* bs = smem;
        int off = ia * 132 + c4;
        *(float4*)(bs + off)        = v1;
        *(float4*)(bs + 2112 + off) = v2;
        float4 e;
        e.x = to_tf32(__expf(c * v3.x)); e.y = to_tf32(__expf(c * v3.y));
        e.z = to_tf32(__expf(c * v3.z)); e.w = to_tf32(__expf(c * v3.w));
        *(float4*)(bs + 4224 + off) = e;
    }
    __syncthreads();

    for (int ch = 0; ch < NCHUNK; ch++) {
        const int s = ch & 1;
        if (ch + 1 < NCHUNK) {
            int i = (ch + 1) * 16 + ia;
            v1 = *(const float4*)(kvb  + (size_t)i * DIM + d0 + c4);
            v2 = *(const float4*)(kwb  + (size_t)i * DIM + d0 + c4);
            v3 = *(const float4*)(disb + (size_t)i * SEQ + j0 + c4);
        }

        const float* bs = smem + s * STG;
        #pragma unroll
        for (int kk = 0; kk < 2; kk++) {
            const float* arow = bs + kk * 8 * 132;
            wmma::fragment<wmma::matrix_a, 16, 16, 8, wmma::precision::tf32, wmma::col_major> a1[2], a2[2];
            wmma::fragment<wmma::matrix_b, 16, 16, 8, wmma::precision::tf32, wmma::row_major> bf[2];
            #pragma unroll
            for (int mt = 0; mt < 2; mt++) {
                wmma::load_matrix_sync(a1[mt], arow + msub + mt * 16, 132);
                wmma::load_matrix_sync(a2[mt], arow + 2112 + msub + mt * 16, 132);
            }
            #pragma unroll
            for (int nt = 0; nt < 2; nt++)
                wmma::load_matrix_sync(bf[nt], arow + 4224 + nsub + nt * 16, 132);
            #pragma unroll
            for (int mt = 0; mt < 2; mt++)
                #pragma unroll
                for (int nt = 0; nt < 2; nt++) {
                    wmma::mma_sync(acc1[mt][nt], a1[mt], bf[nt], acc1[mt][nt]);
                    wmma::mma_sync(acc2[mt][nt], a2[mt], bf[nt], acc2[mt][nt]);
                }
        }

        if (ch + 1 < NCHUNK) {
            float* ns = smem + ((ch + 1) & 1) * STG;
            int off = ia * 132 + c4;
            *(float4*)(ns + off)        = v1;
            *(float4*)(ns + 2112 + off) = v2;
            float4 e;
            e.x = to_tf32(__expf(c * v3.x)); e.y = to_tf32(__expf(c * v3.y));
            e.z = to_tf32(__expf(c * v3.z)); e.w = to_tf32(__expf(c * v3.w));
            *(float4*)(ns + 4224 + off) = e;
        }
        __syncthreads();
    }

    // ----- epilogue: ratio, transpose via mem_col_major store, combine -----
    #pragma unroll
    for (int mt = 0; mt < 2; mt++)
        #pragma unroll
        for (int nt = 0; nt < 2; nt++) {
            #pragma unroll
            for (int e = 0; e < acc1[mt][nt].num_elements; e++)
                acc1[mt][nt].x[e] = __fdividef(acc1[mt][nt].x[e], acc2[mt][nt].x[e]);
            // mem_col_major: element(row=d,col=j) -> ptr[d + j*ldm] => smem[j][d]
            wmma::store_matrix_sync(smem + (size_t)(nsub + nt * 16) * 132 + msub + mt * 16,
                                    acc1[mt][nt], 132, wmma::mem_col_major);
        }
    __syncthreads();

    {
        const int j   = tid >> 2;
        const int seg = (tid & 3) * 32;
        const float* ser = smem + j * 132 + seg;
        const float* sqr = g_sq + ((size_t)b * SEQ + j0 + j) * DIM + d0 + seg;
        float*      outr = out  + ((size_t)b * SEQ + j0 + j) * DIM + d0 + seg;
        #pragma unroll
        for (int q = 0; q < 8; q++) {
            float4 rv = *(const float4*)(ser + q * 4);
            float4 sv = *(const float4*)(sqr + q * 4);
            float4 o;
            o.x = sv.x * rv.x; o.y = sv.y * rv.y;
            o.z = sv.z * rv.z; o.w = sv.w * rv.w;
            *(float4*)(outr + q * 4) = o;
        }
    }
}

// ============================================================================
extern "C" void kernel_launch(void* const* d_in, const int* in_sizes, int n_in,
                              void* d_out, int out_size)
{
    const float* x     = (const float*)d_in[0];
    const float* dis   = (const float*)d_in[1];
    const float* Wq    = (const float*)d_in[2];
    const float* Wk    = (const float*)d_in[3];
    const float* Wv    = (const float*)d_in[4];
    const float* alpha = (const float*)d_in[5];
    float* out = (float*)d_out;

    cudaFuncSetAttribute(agg_wmma, cudaFuncAttributeMaxDynamicSharedMemorySize,
                         AGG_SMEM_BYTES);

    dim3 g1(DIM / 64, (BATCH * SEQ) / 128);   // (8, 128)
    qkv_kernel<<<g1, 256>>>(x, Wq, Wk, Wv);

    dim3 g2(DIM / 128, SEQ / 128, BATCH);     // (4, 16, 8)
    agg_wmma<<<g2, 512, AGG_SMEM_BYTES>>>(dis, alpha, out);
}

// round 5
// speedup vs baseline: 1.2123x; 1.1004x over previous
#include <cuda_runtime.h>
#include <mma.h>
#include <cstdint>

using namespace nvcuda;

#define BATCH 8
#define SEQ   2048
#define DIM   512

// Scratch (__device__ globals per allocation-free rule)
__device__ float g_sq[(size_t)BATCH * SEQ * DIM];   // sigmoid(q)      [b][i][d]
__device__ float g_kw[(size_t)BATCH * SEQ * DIM];   // exp(k) (tf32)   [b][i][d]
__device__ float g_kv[(size_t)BATCH * SEQ * DIM];   // exp(k)*v (tf32) [b][i][d]
__device__ float g_xr[(size_t)BATCH * SEQ * DIM];   // x tf32-rounded
__device__ float g_wr[(size_t)3 * DIM * DIM];       // Wq,Wk,Wv tf32-rounded

// ---------------------------------------------------------------- helpers ---
__device__ __forceinline__ float to_tf32(float x) {
    uint32_t u; asm("cvt.rna.tf32.f32 %0, %1;" : "=r"(u) : "f"(x));
    return __uint_as_float(u);
}
__device__ __forceinline__ uint32_t smem_u32(const void* p) {
    uint32_t a;
    asm("{ .reg .u64 t; cvta.to.shared.u64 t, %1; cvt.u32.u64 %0, t; }" : "=r"(a) : "l"(p));
    return a;
}
#define CP16(dst_u32, src) \
    asm volatile("cp.async.cg.shared.global [%0], [%1], 16;" \
                 :: "r"(dst_u32), "l"(src) : "memory")
#define CP_COMMIT() asm volatile("cp.async.commit_group;" ::: "memory")
#define CP_WAIT0()  asm volatile("cp.async.wait_group 0;" ::: "memory")

// ============================================================================
// Kernel 0: pre-round x and W{q,k,v} to tf32 (rna) into scratch.
// ============================================================================
__global__ __launch_bounds__(256, 8)
void prep_round(const float* __restrict__ x,
                const float* __restrict__ Wq,
                const float* __restrict__ Wk,
                const float* __restrict__ Wv)
{
    size_t t = (size_t)blockIdx.x * blockDim.x + threadIdx.x;
    const size_t NX = (size_t)BATCH * SEQ * DIM / 4;   // 2097152 float4
    const size_t NW = (size_t)DIM * DIM / 4;           // 65536 float4 per mat
    if (t < NX) {
        float4 v = ((const float4*)x)[t];
        v.x = to_tf32(v.x); v.y = to_tf32(v.y); v.z = to_tf32(v.z); v.w = to_tf32(v.w);
        ((float4*)g_xr)[t] = v;
    } else {
        t -= NX;
        if (t < 3 * NW) {
            const float* src = (t < NW) ? Wq : (t < 2 * NW ? Wk : Wv);
            size_t lt = t % NW;
            float4 v = ((const float4*)src)[lt];
            v.x = to_tf32(v.x); v.y = to_tf32(v.y); v.z = to_tf32(v.z); v.w = to_tf32(v.w);
            ((float4*)g_wr)[t] = v;
        }
    }
}

// ============================================================================
// Kernel 1: WMMA tf32 QKV projection + in-fragment nonlinear epilogue.
//   C[m,n] = sum_k x[m,k] * W[n,k]   for W in {Wq,Wk,Wv} (A fragments shared)
//   A = g_xr row_major (xs[m][k], ld 36);  B = g_wr col_major ([n][k], ld 36)
//   CTA 128m x 64n, 256 thr = 8 warps (4m x 2n), warp 32x32, BK=32, cp.async.
//   Epilogue: sigmoid/exp/product elementwise on accumulator fragments
//   (identical mapping across q/k/v), store_matrix_sync direct to global.
// ============================================================================
#define QKV_STAGE_F 11520                      // floats per stage (46080 B)
#define QKV_SMEM (2 * QKV_STAGE_F * 4)         // 92160 B

__global__ __launch_bounds__(256, 1)
void qkv_wmma()
{
    extern __shared__ float sm[];
    const int tid  = threadIdx.x;
    const int wid  = tid >> 5;
    const int wm   = wid & 3, wn = wid >> 2;
    const int msub = wm * 32, nsub = wn * 32;
    const int m0   = blockIdx.y * 128;
    const int n0   = blockIdx.x * 64;
    const uint32_t sb = smem_u32(sm);

    wmma::fragment<wmma::accumulator, 16, 16, 8, float> acc[3][2][2];
    #pragma unroll
    for (int mat = 0; mat < 3; mat++)
        #pragma unroll
        for (int mt = 0; mt < 2; mt++)
            #pragma unroll
            for (int nt = 0; nt < 2; nt++)
                wmma::fill_fragment(acc[mat][mt][nt], 0.0f);

    // -------- cp.async tile issue: x 128x32 (ld36), W 3 x 64x32 (ld36) ------
    auto issue = [&](int s, int k0) {
        uint32_t st = sb + s * (QKV_STAGE_F * 4);
        #pragma unroll
        for (int j = 0; j < 4; j++) {                 // x: 1024 16B chunks
            int id  = tid + j * 256;
            int row = id >> 3, seg = id & 7;
            CP16(st + row * 144 + seg * 16,
                 g_xr + (size_t)(m0 + row) * DIM + k0 + seg * 4);
        }
        #pragma unroll
        for (int j = 0; j < 6; j++) {                 // W: 1536 16B chunks
            int id  = tid + j * 256;
            int mat = id >> 9, r = id & 511;
            int n   = r >> 3, seg = r & 7;
            CP16(st + 18432 + mat * 9216 + n * 144 + seg * 16,
                 g_wr + (size_t)mat * DIM * DIM + (size_t)(n0 + n) * DIM + k0 + seg * 4);
        }
    };

    issue(0, 0); CP_COMMIT(); CP_WAIT0();
    __syncthreads();

    for (int ch = 0; ch < 16; ch++) {
        const int s = ch & 1;
        if (ch < 15) { issue(s ^ 1, (ch + 1) * 32); CP_COMMIT(); }

        const float* xs = sm + s * QKV_STAGE_F;
        const float* ws = xs + 4608;
        #pragma unroll
        for (int kk = 0; kk < 4; kk++) {
            wmma::fragment<wmma::matrix_a, 16, 16, 8, wmma::precision::tf32, wmma::row_major> af[2];
            #pragma unroll
            for (int mt = 0; mt < 2; mt++)
                wmma::load_matrix_sync(af[mt], xs + (msub + mt * 16) * 36 + kk * 8, 36);
            #pragma unroll
            for (int mat = 0; mat < 3; mat++) {
                wmma::fragment<wmma::matrix_b, 16, 16, 8, wmma::precision::tf32, wmma::col_major> bf[2];
                #pragma unroll
                for (int nt = 0; nt < 2; nt++)
                    wmma::load_matrix_sync(bf[nt], ws + mat * 2304 + (nsub + nt * 16) * 36 + kk * 8, 36);
                #pragma unroll
                for (int mt = 0; mt < 2; mt++)
                    #pragma unroll
                    for (int nt = 0; nt < 2; nt++)
                        wmma::mma_sync(acc[mat][mt][nt], af[mt], bf[nt], acc[mat][mt][nt]);
            }
        }
        if (ch < 15) CP_WAIT0();
        __syncthreads();
    }

    // -------- epilogue: elementwise nonlinearity, direct global stores ------
    #pragma unroll
    for (int mt = 0; mt < 2; mt++)
        #pragma unroll
        for (int nt = 0; nt < 2; nt++) {
            auto& q = acc[0][mt][nt];
            auto& k = acc[1][mt][nt];
            auto& v = acc[2][mt][nt];
            #pragma unroll
            for (int e = 0; e < q.num_elements; e++) {
                float sq = 1.0f / (1.0f + __expf(-q.x[e]));
                float kw = __expf(k.x[e]);
                v.x[e] = to_tf32(kw * v.x[e]);
                k.x[e] = to_tf32(kw);
                q.x[e] = sq;
            }
            size_t base = (size_t)(m0 + msub + mt * 16) * DIM + n0 + nsub + nt * 16;
            wmma::store_matrix_sync(g_sq + base, q, DIM, wmma::mem_row_major);
            wmma::store_matrix_sync(g_kw + base, k, DIM, wmma::mem_row_major);
            wmma::store_matrix_sync(g_kv + base, v, DIM, wmma::mem_row_major);
        }
}

// ============================================================================
// Kernel 2: WMMA tf32 dual aggregation GEMM (R4-validated fragments).
//   BK=32, cp.async for kv/kw tiles, LDG+exp+STS for dis, 64 barriers.
//   CTA 128d x 128j, 512 thr = 16 warps (4m x 4n), warp 32x32.
// ============================================================================
#define AGG_STAGE_F 12672                     // floats per stage (50688 B)
#define AGG_SMEM (2 * AGG_STAGE_F * 4)        // 101376 B

__global__ __launch_bounds__(512, 1)
void agg_wmma(const float* __restrict__ dis,
              const float* __restrict__ alpha_p,
              float* __restrict__ out)
{
    extern __shared__ float sm[];
    const int tid = threadIdx.x;
    const int wid = tid >> 5;
    const int b   = blockIdx.z;
    const int j0  = blockIdx.y * 128;
    const int d0  = blockIdx.x * 128;
    const float c = -alpha_p[0] * 11.0f;       // -alpha * log2(2048)
    const int wm = wid & 3, wn = wid >> 2;
    const int msub = wm * 32, nsub = wn * 32;
    const uint32_t sb = smem_u32(sm);

    wmma::fragment<wmma::accumulator, 16, 16, 8, float> acc1[2][2], acc2[2][2];
    #pragma unroll
    for (int mt = 0; mt < 2; mt++)
        #pragma unroll
        for (int nt = 0; nt < 2; nt++) {
            wmma::fill_fragment(acc1[mt][nt], 0.0f);
            wmma::fill_fragment(acc2[mt][nt], 0.0f);
        }

    const float* kvb  = g_kv + (size_t)b * SEQ * DIM;
    const float* kwb  = g_kw + (size_t)b * SEQ * DIM;
    const float* disb = dis  + (size_t)b * SEQ * SEQ;

    // kv/kw stage tiles: 32 i x 128 d, ld 132 (col_major A, R4-validated)
    auto issue = [&](int s, int i0) {
        uint32_t st = sb + s * (AGG_STAGE_F * 4);
        #pragma unroll
        for (int j = 0; j < 2; j++) {            // 1024 chunks per tensor
            int id = tid + j * 512;
            int i = id >> 5, seg = id & 31;
            CP16(st + i * 528 + seg * 16,
                 kvb + (size_t)(i0 + i) * DIM + d0 + seg * 4);
            CP16(st + 16896 + i * 528 + seg * 16,
                 kwb + (size_t)(i0 + i) * DIM + d0 + seg * 4);
        }
    };
    // dis tile: 32 i x 128 j  (LDG -> regs; later exp + STS)
    const int dv_i0 = (tid + 0)   >> 5, dv_q0 = ((tid + 0)   & 31) * 4;
    const int dv_i1 = (tid + 512) >> 5, dv_q1 = ((tid + 512) & 31) * 4;

    float4 dv0, dv1;
    auto ldg_dis = [&](int i0) {
        dv0 = *(const float4*)(disb + (size_t)(i0 + dv_i0) * SEQ + j0 + dv_q0);
        dv1 = *(const float4*)(disb + (size_t)(i0 + dv_i1) * SEQ + j0 + dv_q1);
    };
    auto sts_dis = [&](int s) {
        float* dw = sm + s * AGG_STAGE_F + 8448;
        float4 e;
        e.x = to_tf32(__expf(c * dv0.x)); e.y = to_tf32(__expf(c * dv0.y));
        e.z = to_tf32(__expf(c * dv0.z)); e.w = to_tf32(__expf(c * dv0.w));
        *(float4*)(dw + dv_i0 * 132 + dv_q0) = e;
        e.x = to_tf32(__expf(c * dv1.x)); e.y = to_tf32(__expf(c * dv1.y));
        e.z = to_tf32(__expf(c * dv1.z)); e.w = to_tf32(__expf(c * dv1.w));
        *(float4*)(dw + dv_i1 * 132 + dv_q1) = e;
    };

    // prologue: stage 0 = chunk 0
    issue(0, 0); CP_COMMIT();
    ldg_dis(0); sts_dis(0);
    CP_WAIT0();
    __syncthreads();

    for (int ch = 0; ch < 64; ch++) {
        const int s = ch & 1;
        if (ch < 63) { issue(s ^ 1, (ch + 1) * 32); CP_COMMIT(); ldg_dis((ch + 1) * 32); }

        const float* st = sm + s * AGG_STAGE_F;
        #pragma unroll
        for (int kk = 0; kk < 4; kk++) {
            const float* arow = st + kk * 1056;        // kk*8*132
            wmma::fragment<wmma::matrix_a, 16, 16, 8, wmma::precision::tf32, wmma::col_major> a1[2], a2[2];
            wmma::fragment<wmma::matrix_b, 16, 16, 8, wmma::precision::tf32, wmma::row_major> bf[2];
            #pragma unroll
            for (int mt = 0; mt < 2; mt++) {
                wmma::load_matrix_sync(a1[mt], arow + msub + mt * 16, 132);
                wmma::load_matrix_sync(a2[mt], arow + 4224 + msub + mt * 16, 132);
            }
            #pragma unroll
            for (int nt = 0; nt < 2; nt++)
                wmma::load_matrix_sync(bf[nt], arow + 8448 + nsub + nt * 16, 132);
            #pragma unroll
            for (int mt = 0; mt < 2; mt++)
                #pragma unroll
                for (int nt = 0; nt < 2; nt++) {
                    wmma::mma_sync(acc1[mt][nt], a1[mt], bf[nt], acc1[mt][nt]);
                    wmma::mma_sync(acc2[mt][nt], a2[mt], bf[nt], acc2[mt][nt]);
                }
        }

        if (ch < 63) { sts_dis(s ^ 1); CP_WAIT0(); }
        __syncthreads();
    }

    // ----- epilogue: ratio in-fragment, transpose via mem_col_major -> smem -
    #pragma unroll
    for (int mt = 0; mt < 2; mt++)
        #pragma unroll
        for (int nt = 0; nt < 2; nt++) {
            #pragma unroll
            for (int e = 0; e < acc1[mt][nt].num_elements; e++)
                acc1[mt][nt].x[e] = __fdividef(acc1[mt][nt].x[e], acc2[mt][nt].x[e]);
            wmma::store_matrix_sync(sm + (size_t)(nsub + nt * 16) * 132 + msub + mt * 16,
                                    acc1[mt][nt], 132, wmma::mem_col_major);
        }
    __syncthreads();

    {
        const int j   = tid >> 2;
        const int seg = (tid & 3) * 32;
        const float* ser = sm + j * 132 + seg;
        const float* sqr = g_sq + ((size_t)b * SEQ + j0 + j) * DIM + d0 + seg;
        float*      outr = out  + ((size_t)b * SEQ + j0 + j) * DIM + d0 + seg;
        #pragma unroll
        for (int q = 0; q < 8; q++) {
            float4 rv = *(const float4*)(ser + q * 4);
            float4 sv = *(const float4*)(sqr + q * 4);
            float4 o;
            o.x = sv.x * rv.x; o.y = sv.y * rv.y;
            o.z = sv.z * rv.z; o.w = sv.w * rv.w;
            *(float4*)(outr + q * 4) = o;
        }
    }
}

// ============================================================================
extern "C" void kernel_launch(void* const* d_in, const int* in_sizes, int n_in,
                              void* d_out, int out_size)
{
    const float* x     = (const float*)d_in[0];
    const float* dis   = (const float*)d_in[1];
    const float* Wq    = (const float*)d_in[2];
    const float* Wk    = (const float*)d_in[3];
    const float* Wv    = (const float*)d_in[4];
    const float* alpha = (const float*)d_in[5];
    float* out = (float*)d_out;

    cudaFuncSetAttribute(qkv_wmma, cudaFuncAttributeMaxDynamicSharedMemorySize, QKV_SMEM);
    cudaFuncSetAttribute(agg_wmma, cudaFuncAttributeMaxDynamicSharedMemorySize, AGG_SMEM);

    // prep: round x (2097152 f4) + W (196608 f4)
    prep_round<<<(2097152 + 196608 + 255) / 256, 256>>>(x, Wq, Wk, Wv);

    dim3 g1(DIM / 64, (BATCH * SEQ) / 128);   // (8, 128)
    qkv_wmma<<<g1, 256, QKV_SMEM>>>();

    dim3 g2(DIM / 128, SEQ / 128, BATCH);     // (4, 16, 8)
    agg_wmma<<<g2, 512, AGG_SMEM>>>(dis, alpha, out);
}

// round 7
// speedup vs baseline: 1.2496x; 1.0308x over previous
#include <cuda_runtime.h>
#include <mma.h>
#include <cstdint>

using namespace nvcuda;

#define BATCH 8
#define SEQ   2048
#define DIM   512

// Scratch (__device__ globals per allocation-free rule)
__device__ float g_sq[(size_t)BATCH * SEQ * DIM];   // sigmoid(q)      [b][i][d]
__device__ float g_kw[(size_t)BATCH * SEQ * DIM];   // exp(k) (tf32)   [b][i][d]
__device__ float g_kv[(size_t)BATCH * SEQ * DIM];   // exp(k)*v (tf32) [b][i][d]
__device__ float g_xr[(size_t)BATCH * SEQ * DIM];   // x tf32-rounded
__device__ float g_wr[(size_t)3 * DIM * DIM];       // Wq,Wk,Wv tf32-rounded

// ---------------------------------------------------------------- helpers ---
__device__ __forceinline__ float to_tf32(float x) {
    uint32_t u; asm("cvt.rna.tf32.f32 %0, %1;" : "=r"(u) : "f"(x));
    return __uint_as_float(u);
}
__device__ __forceinline__ uint32_t smem_u32(const void* p) {
    uint32_t a;
    asm("{ .reg .u64 t; cvta.to.shared.u64 t, %1; cvt.u32.u64 %0, t; }" : "=r"(a) : "l"(p));
    return a;
}
#define CP16(dst_u32, src) \
    asm volatile("cp.async.cg.shared.global [%0], [%1], 16;" \
                 :: "r"(dst_u32), "l"(src) : "memory")
#define CP_COMMIT() asm volatile("cp.async.commit_group;" ::: "memory")
#define CP_WAIT0()  asm volatile("cp.async.wait_group 0;" ::: "memory")

// ============================================================================
// Kernel 0: pre-round x and W{q,k,v} to tf32 (rna) into scratch.
// ============================================================================
__global__ __launch_bounds__(256, 8)
void prep_round(const float* __restrict__ x,
                const float* __restrict__ Wq,
                const float* __restrict__ Wk,
                const float* __restrict__ Wv)
{
    size_t t = (size_t)blockIdx.x * blockDim.x + threadIdx.x;
    const size_t NX = (size_t)BATCH * SEQ * DIM / 4;   // 2097152 float4
    const size_t NW = (size_t)DIM * DIM / 4;           // 65536 float4 per mat
    if (t < NX) {
        float4 v = ((const float4*)x)[t];
        v.x = to_tf32(v.x); v.y = to_tf32(v.y); v.z = to_tf32(v.z); v.w = to_tf32(v.w);
        ((float4*)g_xr)[t] = v;
    } else {
        t -= NX;
        if (t < 3 * NW) {
            const float* src = (t < NW) ? Wq : (t < 2 * NW ? Wk : Wv);
            size_t lt = t % NW;
            float4 v = ((const float4*)src)[lt];
            v.x = to_tf32(v.x); v.y = to_tf32(v.y); v.z = to_tf32(v.z); v.w = to_tf32(v.w);
            ((float4*)g_wr)[t] = v;
        }
    }
}

// ============================================================================
// Kernel 1: WMMA tf32 QKV projection + in-fragment nonlinear epilogue.
//   ldm padded 36 -> 40 (ld%32==8 => conflict-free fragment LDS).
//   CTA 128m x 64n, 256 thr = 8 warps (4m x 2n), warp 32x32, BK=32, cp.async.
// ============================================================================
#define QKV_LD 40
#define QKV_STAGE_F 12800                      // 128*40 + 3*64*40 floats
#define QKV_SMEM (2 * QKV_STAGE_F * 4)         // 102400 B

__global__ __launch_bounds__(256, 1)
void qkv_wmma()
{
    extern __shared__ float sm[];
    const int tid  = threadIdx.x;
    const int wid  = tid >> 5;
    const int wm   = wid & 3, wn = wid >> 2;
    const int msub = wm * 32, nsub = wn * 32;
    const int m0   = blockIdx.y * 128;
    const int n0   = blockIdx.x * 64;
    const uint32_t sb = smem_u32(sm);

    wmma::fragment<wmma::accumulator, 16, 16, 8, float> acc[3][2][2];
    #pragma unroll
    for (int mat = 0; mat < 3; mat++)
        #pragma unroll
        for (int mt = 0; mt < 2; mt++)
            #pragma unroll
            for (int nt = 0; nt < 2; nt++)
                wmma::fill_fragment(acc[mat][mt][nt], 0.0f);

    // -------- cp.async tile issue: x 128x32 (ld40), W 3 x 64x32 (ld40) ------
    auto issue = [&](int s, int k0) {
        uint32_t st = sb + s * (QKV_STAGE_F * 4);
        #pragma unroll
        for (int j = 0; j < 4; j++) {                 // x: 1024 16B chunks
            int id  = tid + j * 256;
            int row = id >> 3, seg = id & 7;
            CP16(st + row * (QKV_LD * 4) + seg * 16,
                 g_xr + (size_t)(m0 + row) * DIM + k0 + seg * 4);
        }
        #pragma unroll
        for (int j = 0; j < 6; j++) {                 // W: 1536 16B chunks
            int id  = tid + j * 256;
            int mat = id >> 9, r = id & 511;
            int n   = r >> 3, seg = r & 7;
            CP16(st + 128 * (QKV_LD * 4) + mat * (64 * QKV_LD * 4) + n * (QKV_LD * 4) + seg * 16,
                 g_wr + (size_t)mat * DIM * DIM + (size_t)(n0 + n) * DIM + k0 + seg * 4);
        }
    };

    issue(0, 0); CP_COMMIT(); CP_WAIT0();
    __syncthreads();

    for (int ch = 0; ch < 16; ch++) {
        const int s = ch & 1;
        if (ch < 15) { issue(s ^ 1, (ch + 1) * 32); CP_COMMIT(); }

        const float* xs = sm + s * QKV_STAGE_F;
        const float* ws = xs + 128 * QKV_LD;
        #pragma unroll
        for (int kk = 0; kk < 4; kk++) {
            wmma::fragment<wmma::matrix_a, 16, 16, 8, wmma::precision::tf32, wmma::row_major> af[2];
            #pragma unroll
            for (int mt = 0; mt < 2; mt++)
                wmma::load_matrix_sync(af[mt], xs + (msub + mt * 16) * QKV_LD + kk * 8, QKV_LD);
            #pragma unroll
            for (int mat = 0; mat < 3; mat++) {
                wmma::fragment<wmma::matrix_b, 16, 16, 8, wmma::precision::tf32, wmma::col_major> bf[2];
                #pragma unroll
                for (int nt = 0; nt < 2; nt++)
                    wmma::load_matrix_sync(bf[nt], ws + mat * (64 * QKV_LD) + (nsub + nt * 16) * QKV_LD + kk * 8, QKV_LD);
                #pragma unroll
                for (int mt = 0; mt < 2; mt++)
                    #pragma unroll
                    for (int nt = 0; nt < 2; nt++)
                        wmma::mma_sync(acc[mat][mt][nt], af[mt], bf[nt], acc[mat][mt][nt]);
            }
        }
        if (ch < 15) CP_WAIT0();
        __syncthreads();
    }

    // -------- epilogue: elementwise nonlinearity, direct global stores ------
    #pragma unroll
    for (int mt = 0; mt < 2; mt++)
        #pragma unroll
        for (int nt = 0; nt < 2; nt++) {
            auto& q = acc[0][mt][nt];
            auto& k = acc[1][mt][nt];
            auto& v = acc[2][mt][nt];
            #pragma unroll
            for (int e = 0; e < q.num_elements; e++) {
                float sq = 1.0f / (1.0f + __expf(-q.x[e]));
                float kw = __expf(k.x[e]);
                v.x[e] = to_tf32(kw * v.x[e]);
                k.x[e] = to_tf32(kw);
                q.x[e] = sq;
            }
            size_t base = (size_t)(m0 + msub + mt * 16) * DIM + n0 + nsub + nt * 16;
            wmma::store_matrix_sync(g_sq + base, q, DIM, wmma::mem_row_major);
            wmma::store_matrix_sync(g_kw + base, k, DIM, wmma::mem_row_major);
            wmma::store_matrix_sync(g_kv + base, v, DIM, wmma::mem_row_major);
        }
}

// ============================================================================
// Kernel 2: WMMA tf32 dual aggregation GEMM.
//   ldm padded 132 -> 136 (conflict-free fragment LDS).
//   BK=32, cp.async for kv/kw tiles, LDG+exp+STS for dis, 64 barriers.
//   CTA 128d x 128j, 512 thr = 16 warps (4m x 4n), warp 32x32.
// ============================================================================
#define AGG_LD 136
#define AGG_STAGE_F (3 * 32 * AGG_LD)          // 13056 floats (52224 B)
#define AGG_SMEM (2 * AGG_STAGE_F * 4)         // 104448 B

__global__ __launch_bounds__(512, 1)
void agg_wmma(const float* __restrict__ dis,
              const float* __restrict__ alpha_p,
              float* __restrict__ out)
{
    extern __shared__ float sm[];
    const int tid = threadIdx.x;
    const int wid = tid >> 5;
    const int b   = blockIdx.z;
    const int j0  = blockIdx.y * 128;
    const int d0  = blockIdx.x * 128;
    const float c = -alpha_p[0] * 11.0f;       // -alpha * log2(2048)
    const int wm = wid & 3, wn = wid >> 2;
    const int msub = wm * 32, nsub = wn * 32;
    const uint32_t sb = smem_u32(sm);

    wmma::fragment<wmma::accumulator, 16, 16, 8, float> acc1[2][2], acc2[2][2];
    #pragma unroll
    for (int mt = 0; mt < 2; mt++)
        #pragma unroll
        for (int nt = 0; nt < 2; nt++) {
            wmma::fill_fragment(acc1[mt][nt], 0.0f);
            wmma::fill_fragment(acc2[mt][nt], 0.0f);
        }

    const float* kvb  = g_kv + (size_t)b * SEQ * DIM;
    const float* kwb  = g_kw + (size_t)b * SEQ * DIM;
    const float* disb = dis  + (size_t)b * SEQ * SEQ;

    // kv/kw stage tiles: 32 i x 128 d, ld 136 (col_major A)
    auto issue = [&](int s, int i0) {
        uint32_t st = sb + s * (AGG_STAGE_F * 4);
        #pragma unroll
        for (int j = 0; j < 2; j++) {            // 1024 chunks per tensor
            int id = tid + j * 512;
            int i = id >> 5, seg = id & 31;
            CP16(st + i * (AGG_LD * 4) + seg * 16,
                 kvb + (size_t)(i0 + i) * DIM + d0 + seg * 4);
            CP16(st + 32 * (AGG_LD * 4) + i * (AGG_LD * 4) + seg * 16,
                 kwb + (size_t)(i0 + i) * DIM + d0 + seg * 4);
        }
    };
    // dis tile: 32 i x 128 j  (LDG -> regs; later exp + STS)
    const int dv_i0 = (tid + 0)   >> 5, dv_q0 = ((tid + 0)   & 31) * 4;
    const int dv_i1 = (tid + 512) >> 5, dv_q1 = ((tid + 512) & 31) * 4;

    float4 dv0, dv1;
    auto ldg_dis = [&](int i0) {
        dv0 = *(const float4*)(disb + (size_t)(i0 + dv_i0) * SEQ + j0 + dv_q0);
        dv1 = *(const float4*)(disb + (size_t)(i0 + dv_i1) * SEQ + j0 + dv_q1);
    };
    auto sts_dis = [&](int s) {
        float* dw = sm + s * AGG_STAGE_F + 64 * AGG_LD;
        float4 e;
        e.x = to_tf32(__expf(c * dv0.x)); e.y = to_tf32(__expf(c * dv0.y));
        e.z = to_tf32(__expf(c * dv0.z)); e.w = to_tf32(__expf(c * dv0.w));
        *(float4*)(dw + dv_i0 * AGG_LD + dv_q0) = e;
        e.x = to_tf32(__expf(c * dv1.x)); e.y = to_tf32(__expf(c * dv1.y));
        e.z = to_tf32(__expf(c * dv1.z)); e.w = to_tf32(__expf(c * dv1.w));
        *(float4*)(dw + dv_i1 * AGG_LD + dv_q1) = e;
    };

    // prologue: stage 0 = chunk 0
    issue(0, 0); CP_COMMIT();
    ldg_dis(0); sts_dis(0);
    CP_WAIT0();
    __syncthreads();

    for (int ch = 0; ch < 64; ch++) {
        const int s = ch & 1;
        if (ch < 63) { issue(s ^ 1, (ch + 1) * 32); CP_COMMIT(); ldg_dis((ch + 1) * 32); }

        const float* st = sm + s * AGG_STAGE_F;
        #pragma unroll
        for (int kk = 0; kk < 4; kk++) {
            const float* arow = st + kk * 8 * AGG_LD;
            wmma::fragment<wmma::matrix_a, 16, 16, 8, wmma::precision::tf32, wmma::col_major> a1[2], a2[2];
            wmma::fragment<wmma::matrix_b, 16, 16, 8, wmma::precision::tf32, wmma::row_major> bf[2];
            #pragma unroll
            for (int mt = 0; mt < 2; mt++) {
                wmma::load_matrix_sync(a1[mt], arow + msub + mt * 16, AGG_LD);
                wmma::load_matrix_sync(a2[mt], arow + 32 * AGG_LD + msub + mt * 16, AGG_LD);
            }
            #pragma unroll
            for (int nt = 0; nt < 2; nt++)
                wmma::load_matrix_sync(bf[nt], arow + 64 * AGG_LD + nsub + nt * 16, AGG_LD);
            #pragma unroll
            for (int mt = 0; mt < 2; mt++)
                #pragma unroll
                for (int nt = 0; nt < 2; nt++) {
                    wmma::mma_sync(acc1[mt][nt], a1[mt], bf[nt], acc1[mt][nt]);
                    wmma::mma_sync(acc2[mt][nt], a2[mt], bf[nt], acc2[mt][nt]);
                }
        }

        if (ch < 63) { sts_dis(s ^ 1); CP_WAIT0(); }
        __syncthreads();
    }

    // ----- epilogue: ratio in-fragment, transpose via mem_col_major -> smem -
    #pragma unroll
    for (int mt = 0; mt < 2; mt++)
        #pragma unroll
        for (int nt = 0; nt < 2; nt++) {
            #pragma unroll
            for (int e = 0; e < acc1[mt][nt].num_elements; e++)
                acc1[mt][nt].x[e] = __fdividef(acc1[mt][nt].x[e], acc2[mt][nt].x[e]);
            wmma::store_matrix_sync(sm + (size_t)(nsub + nt * 16) * AGG_LD + msub + mt * 16,
                                    acc1[mt][nt], AGG_LD, wmma::mem_col_major);
        }
    __syncthreads();

    {
        const int j   = tid >> 2;
        const int seg = (tid & 3) * 32;
        const float* ser = sm + j * AGG_LD + seg;
        const float* sqr = g_sq + ((size_t)b * SEQ + j0 + j) * DIM + d0 + seg;
        float*      outr = out  + ((size_t)b * SEQ + j0 + j) * DIM + d0 + seg;
        #pragma unroll
        for (int q = 0; q < 8; q++) {
            float4 rv = *(const float4*)(ser + q * 4);
            float4 sv = *(const float4*)(sqr + q * 4);
            float4 o;
            o.x = sv.x * rv.x; o.y = sv.y * rv.y;
            o.z = sv.z * rv.z; o.w = sv.w * rv.w;
            *(float4*)(outr + q * 4) = o;
        }
    }
}

// ============================================================================
extern "C" void kernel_launch(void* const* d_in, const int* in_sizes, int n_in,
                              void* d_out, int out_size)
{
    const float* x     = (const float*)d_in[0];
    const float* dis   = (const float*)d_in[1];
    const float* Wq    = (const float*)d_in[2];
    const float* Wk    = (const float*)d_in[3];
    const float* Wv    = (const float*)d_in[4];
    const float* alpha = (const float*)d_in[5];
    float* out = (float*)d_out;

    cudaFuncSetAttribute(qkv_wmma, cudaFuncAttributeMaxDynamicSharedMemorySize, QKV_SMEM);
    cudaFuncSetAttribute(agg_wmma, cudaFuncAttributeMaxDynamicSharedMemorySize, AGG_SMEM);

    // prep: round x (2097152 f4) + W (196608 f4)
    prep_round<<<(2097152 + 196608 + 255) / 256, 256>>>(x, Wq, Wk, Wv);

    dim3 g1(DIM / 64, (BATCH * SEQ) / 128);   // (8, 128)
    qkv_wmma<<<g1, 256, QKV_SMEM>>>();

    dim3 g2(DIM / 128, SEQ / 128, BATCH);     // (4, 16, 8)
    agg_wmma<<<g2, 512, AGG_SMEM>>>(dis, alpha, out);
}

// round 10
// speedup vs baseline: 2.5607x; 2.0492x over previous
#include <cuda_runtime.h>
#include <cuda_fp16.h>
#include <mma.h>
#include <cstdint>

using namespace nvcuda;

#define BATCH 8
#define SEQ   2048
#define DIM   512

// Scratch (__device__ globals per allocation-free rule)
__device__ float  g_sq [(size_t)BATCH * SEQ * DIM];  // sigmoid(q)  [b][i][d] fp32
__device__ __half g_kwh[(size_t)BATCH * SEQ * DIM];  // exp(k)      [b][i][d] fp16
__device__ __half g_kvh[(size_t)BATCH * SEQ * DIM];  // exp(k)*v    [b][i][d] fp16
__device__ __half g_xh [(size_t)BATCH * SEQ * DIM];  // x  fp16
__device__ __half g_wh [(size_t)3 * DIM * DIM];      // Wq,Wk,Wv fp16

// ---------------------------------------------------------------- helpers ---
__device__ __forceinline__ uint32_t smem_u32(const void* p) {
    uint32_t a;
    asm("{ .reg .u64 t; cvta.to.shared.u64 t, %1; cvt.u32.u64 %0, t; }" : "=r"(a) : "l"(p));
    return a;
}
#define CP16(dst_u32, src) \
    asm volatile("cp.async.cg.shared.global [%0], [%1], 16;" \
                 :: "r"(dst_u32), "l"(src) : "memory")
#define CP_COMMIT() asm volatile("cp.async.commit_group;" ::: "memory")
#define CP_WAIT0()  asm volatile("cp.async.wait_group 0;" ::: "memory")

// ============================================================================
// Kernel 0: convert x and W{q,k,v} to fp16 (rn) into scratch.
// ============================================================================
__global__ __launch_bounds__(256, 8)
void prep_half(const float* __restrict__ x,
               const float* __restrict__ Wq,
               const float* __restrict__ Wk,
               const float* __restrict__ Wv)
{
    size_t t = (size_t)blockIdx.x * blockDim.x + threadIdx.x;
    const size_t NX = (size_t)BATCH * SEQ * DIM / 4;   // 2097152 float4
    const size_t NW = (size_t)DIM * DIM / 4;           // 65536 float4 per mat
    if (t < NX) {
        float4 v = ((const float4*)x)[t];
        __half2 h0 = __floats2half2_rn(v.x, v.y);
        __half2 h1 = __floats2half2_rn(v.z, v.w);
        __half2* dst = (__half2*)(g_xh + t * 4);
        dst[0] = h0; dst[1] = h1;
    } else {
        t -= NX;
        if (t < 3 * NW) {
            const float* src = (t < NW) ? Wq : (t < 2 * NW ? Wk : Wv);
            size_t lt = t % NW;
            float4 v = ((const float4*)src)[lt];
            __half2 h0 = __floats2half2_rn(v.x, v.y);
            __half2 h1 = __floats2half2_rn(v.z, v.w);
            __half2* dst = (__half2*)(g_wh + t * 4);
            dst[0] = h0; dst[1] = h1;
        }
    }
}

// ============================================================================
// Kernel 1: WMMA fp16 QKV projection + nonlinear epilogue.
//   C[m,n] = sum_k x[m,k] * W[n,k]   (A row_major, B col_major, fp32 acc)
//   CTA 128m x 64n, 256 thr = 8 warps (4m x 2n), warp 32x32, BK=32 (2 k16).
//   ld = 40 halves (80 B row stride: LDSM 16B segments tile all 32 banks).
//   Epilogue via fp32 smem staging: sigmoid->g_sq, exp->g_kwh, exp*v->g_kvh.
// ============================================================================
#define QKV_LDH 40
#define QKV_STAGE_H (128 * QKV_LDH + 3 * 64 * QKV_LDH)  // 12800 halves
#define QKV_SMEM (2 * QKV_STAGE_H * 2)                  // 51200 B (>= 36864 staging)

__global__ __launch_bounds__(256, 1)
void qkv_wmma()
{
    extern __shared__ char smraw[];
    __half* smh = (__half*)smraw;
    float*  smf = (float*)smraw;
    const int tid  = threadIdx.x;
    const int wid  = tid >> 5;
    const int wm   = wid & 3, wn = wid >> 2;
    const int msub = wm * 32, nsub = wn * 32;
    const int m0   = blockIdx.y * 128;
    const int n0   = blockIdx.x * 64;
    const uint32_t sb = smem_u32(smraw);

    wmma::fragment<wmma::accumulator, 16, 16, 16, float> acc[3][2][2];
    #pragma unroll
    for (int mat = 0; mat < 3; mat++)
        #pragma unroll
        for (int mt = 0; mt < 2; mt++)
            #pragma unroll
            for (int nt = 0; nt < 2; nt++)
                wmma::fill_fragment(acc[mat][mt][nt], 0.0f);

    // x: 128 rows x 32 halves (4 x 16B chunks); W: 3 x 64 x 32 halves
    auto issue = [&](int s, int k0) {
        uint32_t st = sb + s * (QKV_STAGE_H * 2);
        #pragma unroll
        for (int j = 0; j < 2; j++) {                 // x: 512 chunks
            int id  = tid * 2 + j;
            int row = id >> 2, seg = id & 3;
            CP16(st + row * (QKV_LDH * 2) + seg * 16,
                 g_xh + (size_t)(m0 + row) * DIM + k0 + seg * 8);
        }
        #pragma unroll
        for (int j = 0; j < 3; j++) {                 // W: 768 chunks
            int id  = tid + j * 256;
            int mat = id >> 8, r = id & 255;
            int n   = r >> 2, seg = r & 3;
            CP16(st + 128 * (QKV_LDH * 2) + mat * (64 * QKV_LDH * 2) + n * (QKV_LDH * 2) + seg * 16,
                 g_wh + (size_t)mat * DIM * DIM + (size_t)(n0 + n) * DIM + k0 + seg * 8);
        }
    };

    issue(0, 0); CP_COMMIT(); CP_WAIT0();
    __syncthreads();

    for (int ch = 0; ch < 16; ch++) {
        const int s = ch & 1;
        if (ch < 15) { issue(s ^ 1, (ch + 1) * 32); CP_COMMIT(); }

        const __half* xs = smh + s * QKV_STAGE_H;
        const __half* ws = xs + 128 * QKV_LDH;
        #pragma unroll
        for (int kk = 0; kk < 2; kk++) {
            wmma::fragment<wmma::matrix_a, 16, 16, 16, __half, wmma::row_major> af[2];
            #pragma unroll
            for (int mt = 0; mt < 2; mt++)
                wmma::load_matrix_sync(af[mt], xs + (msub + mt * 16) * QKV_LDH + kk * 16, QKV_LDH);
            #pragma unroll
            for (int mat = 0; mat < 3; mat++) {
                wmma::fragment<wmma::matrix_b, 16, 16, 16, __half, wmma::col_major> bf[2];
                #pragma unroll
                for (int nt = 0; nt < 2; nt++)
                    wmma::load_matrix_sync(bf[nt], ws + mat * (64 * QKV_LDH) + (nsub + nt * 16) * QKV_LDH + kk * 16, QKV_LDH);
                #pragma unroll
                for (int mt = 0; mt < 2; mt++)
                    #pragma unroll
                    for (int nt = 0; nt < 2; nt++)
                        wmma::mma_sync(acc[mat][mt][nt], af[mt], bf[nt], acc[mat][mt][nt]);
            }
        }
        if (ch < 15) CP_WAIT0();
        __syncthreads();
    }

    // ---- epilogue: stage each matrix through fp32 smem (ld 72), convert ----
    const int er = tid >> 1;                    // row 0..127
    const int eh = (tid & 1) * 32;              // col half 0/32
    float kwreg[32];

    #pragma unroll
    for (int mat = 0; mat < 3; mat++) {
        #pragma unroll
        for (int mt = 0; mt < 2; mt++)
            #pragma unroll
            for (int nt = 0; nt < 2; nt++)
                wmma::store_matrix_sync(smf + (size_t)(msub + mt * 16) * 72 + nsub + nt * 16,
                                        acc[mat][mt][nt], 72, wmma::mem_row_major);
        __syncthreads();

        const float* src = smf + er * 72 + eh;
        size_t gbase = (size_t)(m0 + er) * DIM + n0 + eh;
        if (mat == 0) {           // sigmoid(q) -> fp32
            #pragma unroll
            for (int q = 0; q < 8; q++) {
                float4 v = *(const float4*)(src + q * 4);
                float4 o;
                o.x = 1.0f / (1.0f + __expf(-v.x));
                o.y = 1.0f / (1.0f + __expf(-v.y));
                o.z = 1.0f / (1.0f + __expf(-v.z));
                o.w = 1.0f / (1.0f + __expf(-v.w));
                *(float4*)(g_sq + gbase + q * 4) = o;
            }
        } else if (mat == 1) {    // exp(k) -> fp16, stash fp32
            #pragma unroll
            for (int q = 0; q < 8; q++) {
                float4 v = *(const float4*)(src + q * 4);
                float4 e;
                e.x = __expf(v.x); e.y = __expf(v.y);
                e.z = __expf(v.z); e.w = __expf(v.w);
                kwreg[q * 4 + 0] = e.x; kwreg[q * 4 + 1] = e.y;
                kwreg[q * 4 + 2] = e.z; kwreg[q * 4 + 3] = e.w;
                __half2* dst = (__half2*)(g_kwh + gbase + q * 4);
                dst[0] = __floats2half2_rn(e.x, e.y);
                dst[1] = __floats2half2_rn(e.z, e.w);
            }
        } else {                  // exp(k)*v -> fp16
            #pragma unroll
            for (int q = 0; q < 8; q++) {
                float4 v = *(const float4*)(src + q * 4);
                __half2* dst = (__half2*)(g_kvh + gbase + q * 4);
                dst[0] = __floats2half2_rn(kwreg[q * 4 + 0] * v.x, kwreg[q * 4 + 1] * v.y);
                dst[1] = __floats2half2_rn(kwreg[q * 4 + 2] * v.z, kwreg[q * 4 + 3] * v.w);
            }
        }
        __syncthreads();
    }
}

// ============================================================================
// Kernel 2: WMMA fp16 dual aggregation GEMM.
//   C1[d,j] = sum_i kv[i,d]*dw[i,j],  C2 with kw.  BK=32 (2 k16), 64 chunks.
//   A = kv/kw [i][d] col_major fp16 (ld 168: 336 B stride, conflict-free LDSM)
//   B = exp(c*dis[i][j]) row_major fp16 (ld 168), shared by both GEMMs.
//   CTA 128d x 128j, 512 thr = 16 warps (4m x 4n), warp 32x32, fp32 acc.
// ============================================================================
#define AGG_LDH 168
#define AGG_STAGE_H (3 * 32 * AGG_LDH)         // 16128 halves (32256 B)
#define AGG_EPI_LD 136
#define AGG_SMEM (128 * AGG_EPI_LD * 4)        // 69632 B (>= 2*32256 = 64512)

__global__ __launch_bounds__(512, 1)
void agg_wmma(const float* __restrict__ dis,
              const float* __restrict__ alpha_p,
              float* __restrict__ out)
{
    extern __shared__ char smraw[];
    __half* smh = (__half*)smraw;
    float*  smf = (float*)smraw;
    const int tid = threadIdx.x;
    const int wid = tid >> 5;
    const int b   = blockIdx.z;
    const int j0  = blockIdx.y * 128;
    const int d0  = blockIdx.x * 128;
    const float c = -alpha_p[0] * 11.0f;       // -alpha * log2(2048)
    const int wm = wid & 3, wn = wid >> 2;
    const int msub = wm * 32, nsub = wn * 32;
    const uint32_t sb = smem_u32(smraw);

    wmma::fragment<wmma::accumulator, 16, 16, 16, float> acc1[2][2], acc2[2][2];
    #pragma unroll
    for (int mt = 0; mt < 2; mt++)
        #pragma unroll
        for (int nt = 0; nt < 2; nt++) {
            wmma::fill_fragment(acc1[mt][nt], 0.0f);
            wmma::fill_fragment(acc2[mt][nt], 0.0f);
        }

    const __half* kvb  = g_kvh + (size_t)b * SEQ * DIM;
    const __half* kwb  = g_kwh + (size_t)b * SEQ * DIM;
    const float*  disb = dis   + (size_t)b * SEQ * SEQ;

    // kv/kw tiles: 32 i x 128 d halves (16 x 16B chunks per row)
    auto issue = [&](int s, int i0) {
        uint32_t st = sb + s * (AGG_STAGE_H * 2);
        int i = tid >> 4, seg = tid & 15;
        CP16(st + i * (AGG_LDH * 2) + seg * 16,
             kvb + (size_t)(i0 + i) * DIM + d0 + seg * 8);
        CP16(st + 32 * (AGG_LDH * 2) + i * (AGG_LDH * 2) + seg * 16,
             kwb + (size_t)(i0 + i) * DIM + d0 + seg * 8);
    };
    // dis tile: 32 i x 128 j  (LDG fp32 -> exp -> fp16 STS)
    const int dv_i0 = (tid + 0)   >> 5, dv_q0 = ((tid + 0)   & 31) * 4;
    const int dv_i1 = (tid + 512) >> 5, dv_q1 = ((tid + 512) & 31) * 4;

    float4 dv0, dv1;
    auto ldg_dis = [&](int i0) {
        dv0 = *(const float4*)(disb + (size_t)(i0 + dv_i0) * SEQ + j0 + dv_q0);
        dv1 = *(const float4*)(disb + (size_t)(i0 + dv_i1) * SEQ + j0 + dv_q1);
    };
    auto sts_dis = [&](int s) {
        __half* dw = smh + s * AGG_STAGE_H + 2 * 32 * AGG_LDH;
        __half2* p0 = (__half2*)(dw + dv_i0 * AGG_LDH + dv_q0);
        p0[0] = __floats2half2_rn(__expf(c * dv0.x), __expf(c * dv0.y));
        p0[1] = __floats2half2_rn(__expf(c * dv0.z), __expf(c * dv0.w));
        __half2* p1 = (__half2*)(dw + dv_i1 * AGG_LDH + dv_q1);
        p1[0] = __floats2half2_rn(__expf(c * dv1.x), __expf(c * dv1.y));
        p1[1] = __floats2half2_rn(__expf(c * dv1.z), __expf(c * dv1.w));
    };

    issue(0, 0); CP_COMMIT();
    ldg_dis(0); sts_dis(0);
    CP_WAIT0();
    __syncthreads();

    for (int ch = 0; ch < 64; ch++) {
        const int s = ch & 1;
        if (ch < 63) { issue(s ^ 1, (ch + 1) * 32); CP_COMMIT(); ldg_dis((ch + 1) * 32); }

        const __half* st = smh + s * AGG_STAGE_H;
        const __half* kwst = st + 32 * AGG_LDH;
        const __half* dwst = st + 2 * 32 * AGG_LDH;
        #pragma unroll
        for (int kk = 0; kk < 2; kk++) {
            wmma::fragment<wmma::matrix_a, 16, 16, 16, __half, wmma::col_major> a1[2], a2[2];
            wmma::fragment<wmma::matrix_b, 16, 16, 16, __half, wmma::row_major> bf[2];
            #pragma unroll
            for (int mt = 0; mt < 2; mt++) {
                wmma::load_matrix_sync(a1[mt], st   + (size_t)(kk * 16) * AGG_LDH + msub + mt * 16, AGG_LDH);
                wmma::load_matrix_sync(a2[mt], kwst + (size_t)(kk * 16) * AGG_LDH + msub + mt * 16, AGG_LDH);
            }
            #pragma unroll
            for (int nt = 0; nt < 2; nt++)
                wmma::load_matrix_sync(bf[nt], dwst + (size_t)(kk * 16) * AGG_LDH + nsub + nt * 16, AGG_LDH);
            #pragma unroll
            for (int mt = 0; mt < 2; mt++)
                #pragma unroll
                for (int nt = 0; nt < 2; nt++) {
                    wmma::mma_sync(acc1[mt][nt], a1[mt], bf[nt], acc1[mt][nt]);
                    wmma::mma_sync(acc2[mt][nt], a2[mt], bf[nt], acc2[mt][nt]);
                }
        }

        if (ch < 63) { sts_dis(s ^ 1); CP_WAIT0(); }
        __syncthreads();
    }

    // ----- epilogue: ratio in-fragment, transpose via mem_col_major -> smem -
    #pragma unroll
    for (int mt = 0; mt < 2; mt++)
        #pragma unroll
        for (int nt = 0; nt < 2; nt++) {
            #pragma unroll
            for (int e = 0; e < acc1[mt][nt].num_elements; e++)
                acc1[mt][nt].x[e] = __fdividef(acc1[mt][nt].x[e], acc2[mt][nt].x[e]);
            wmma::store_matrix_sync(smf + (size_t)(nsub + nt * 16) * AGG_EPI_LD + msub + mt * 16,
                                    acc1[mt][nt], AGG_EPI_LD, wmma::mem_col_major);
        }
    __syncthreads();

    {
        const int j   = tid >> 2;
        const int seg = (tid & 3) * 32;
        const float* ser = smf + j * AGG_EPI_LD + seg;
        const float* sqr = g_sq + ((size_t)b * SEQ + j0 + j) * DIM + d0 + seg;
        float*      outr = out  + ((size_t)b * SEQ + j0 + j) * DIM + d0 + seg;
        #pragma unroll
        for (int q = 0; q < 8; q++) {
            float4 rv = *(const float4*)(ser + q * 4);
            float4 sv = *(const float4*)(sqr + q * 4);
            float4 o;
            o.x = sv.x * rv.x; o.y = sv.y * rv.y;
            o.z = sv.z * rv.z; o.w = sv.w * rv.w;
            *(float4*)(outr + q * 4) = o;
        }
    }
}

// ============================================================================
extern "C" void kernel_launch(void* const* d_in, const int* in_sizes, int n_in,
                              void* d_out, int out_size)
{
    const float* x     = (const float*)d_in[0];
    const float* dis   = (const float*)d_in[1];
    const float* Wq    = (const float*)d_in[2];
    const float* Wk    = (const float*)d_in[3];
    const float* Wv    = (const float*)d_in[4];
    const float* alpha = (const float*)d_in[5];
    float* out = (float*)d_out;

    cudaFuncSetAttribute(qkv_wmma, cudaFuncAttributeMaxDynamicSharedMemorySize, QKV_SMEM);
    cudaFuncSetAttribute(agg_wmma, cudaFuncAttributeMaxDynamicSharedMemorySize, AGG_SMEM);

    prep_half<<<(2097152 + 196608 + 255) / 256, 256>>>(x, Wq, Wk, Wv);

    dim3 g1(DIM / 64, (BATCH * SEQ) / 128);   // (8, 128)
    qkv_wmma<<<g1, 256, QKV_SMEM>>>();

    dim3 g2(DIM / 128, SEQ / 128, BATCH);     // (4, 16, 8)
    agg_wmma<<<g2, 512, AGG_SMEM>>>(dis, alpha, out);
}

// round 12
// speedup vs baseline: 4.3687x; 1.7061x over previous
#include <cuda_runtime.h>
#include <cuda_fp16.h>
#include <mma.h>
#include <cstdint>

using namespace nvcuda;

#define BATCH 8
#define SEQ   2048
#define DIM   512

// Scratch (__device__ globals per allocation-free rule)
__device__ float  g_sq [(size_t)BATCH * SEQ * DIM];  // sigmoid(q)  [b][i][d] fp32
__device__ __half g_kwh[(size_t)BATCH * SEQ * DIM];  // exp(k)      [b][i][d] fp16
__device__ __half g_kvh[(size_t)BATCH * SEQ * DIM];  // exp(k)*v    [b][i][d] fp16
__device__ __half g_xh [(size_t)BATCH * SEQ * DIM];  // x  fp16
__device__ __half g_wh [(size_t)3 * DIM * DIM];      // Wq,Wk,Wv fp16

// ---------------------------------------------------------------- helpers ---
__device__ __forceinline__ uint32_t smem_u32(const void* p) {
    uint32_t a;
    asm("{ .reg .u64 t; cvta.to.shared.u64 t, %1; cvt.u32.u64 %0, t; }" : "=r"(a) : "l"(p));
    return a;
}
#define CP16(dst_u32, src) \
    asm volatile("cp.async.cg.shared.global [%0], [%1], 16;" \
                 :: "r"(dst_u32), "l"(src) : "memory")
#define CP_COMMIT() asm volatile("cp.async.commit_group;" ::: "memory")
#define CP_WAIT0()  asm volatile("cp.async.wait_group 0;" ::: "memory")

// ============================================================================
// Kernel 0: convert x and W{q,k,v} to fp16 (rn) into scratch.
// ============================================================================
__global__ __launch_bounds__(256, 8)
void prep_half(const float* __restrict__ x,
               const float* __restrict__ Wq,
               const float* __restrict__ Wk,
               const float* __restrict__ Wv)
{
    size_t t = (size_t)blockIdx.x * blockDim.x + threadIdx.x;
    const size_t NX = (size_t)BATCH * SEQ * DIM / 4;   // 2097152 float4
    const size_t NW = (size_t)DIM * DIM / 4;           // 65536 float4 per mat
    if (t < NX) {
        float4 v = ((const float4*)x)[t];
        __half2 h0 = __floats2half2_rn(v.x, v.y);
        __half2 h1 = __floats2half2_rn(v.z, v.w);
        __half2* dst = (__half2*)(g_xh + t * 4);
        dst[0] = h0; dst[1] = h1;
    } else {
        t -= NX;
        if (t < 3 * NW) {
            const float* src = (t < NW) ? Wq : (t < 2 * NW ? Wk : Wv);
            size_t lt = t % NW;
            float4 v = ((const float4*)src)[lt];
            __half2 h0 = __floats2half2_rn(v.x, v.y);
            __half2 h1 = __floats2half2_rn(v.z, v.w);
            __half2* dst = (__half2*)(g_wh + t * 4);
            dst[0] = h0; dst[1] = h1;
        }
    }
}

// ============================================================================
// Kernel 1: WMMA fp16 QKV projection + nonlinear epilogue.
//   BK=64 (4 x k16 per chunk, 8 chunks, 8 barriers).
//   ld = 72 halves (144 B stride: 16B segments hit all 8 phases).
// ============================================================================
#define QKV_LDH 72
#define QKV_STAGE_H (128 * QKV_LDH + 3 * 64 * QKV_LDH)  // 23040 halves
#define QKV_SMEM (2 * QKV_STAGE_H * 2)                  // 92160 B

__global__ __launch_bounds__(256, 1)
void qkv_wmma()
{
    extern __shared__ char smraw[];
    __half* smh = (__half*)smraw;
    float*  smf = (float*)smraw;
    const int tid  = threadIdx.x;
    const int wid  = tid >> 5;
    const int wm   = wid & 3, wn = wid >> 2;
    const int msub = wm * 32, nsub = wn * 32;
    const int m0   = blockIdx.y * 128;
    const int n0   = blockIdx.x * 64;
    const uint32_t sb = smem_u32(smraw);

    wmma::fragment<wmma::accumulator, 16, 16, 16, float> acc[3][2][2];
    #pragma unroll
    for (int mat = 0; mat < 3; mat++)
        #pragma unroll
        for (int mt = 0; mt < 2; mt++)
            #pragma unroll
            for (int nt = 0; nt < 2; nt++)
                wmma::fill_fragment(acc[mat][mt][nt], 0.0f);

    // x: 128 rows x 64 halves (8 x 16B); W: 3 x 64 x 64 halves
    auto issue = [&](int s, int k0) {
        uint32_t st = sb + s * (QKV_STAGE_H * 2);
        #pragma unroll
        for (int j = 0; j < 4; j++) {                 // x: 1024 chunks
            int id  = tid + j * 256;
            int row = id >> 3, seg = id & 7;
            CP16(st + row * (QKV_LDH * 2) + seg * 16,
                 g_xh + (size_t)(m0 + row) * DIM + k0 + seg * 8);
        }
        #pragma unroll
        for (int j = 0; j < 6; j++) {                 // W: 1536 chunks
            int id  = tid + j * 256;
            int mat = id >> 9, r = id & 511;
            int n   = r >> 3, seg = r & 7;
            CP16(st + 128 * (QKV_LDH * 2) + mat * (64 * QKV_LDH * 2) + n * (QKV_LDH * 2) + seg * 16,
                 g_wh + (size_t)mat * DIM * DIM + (size_t)(n0 + n) * DIM + k0 + seg * 8);
        }
    };

    issue(0, 0); CP_COMMIT(); CP_WAIT0();
    __syncthreads();

    for (int ch = 0; ch < 8; ch++) {
        const int s = ch & 1;
        if (ch < 7) { issue(s ^ 1, (ch + 1) * 64); CP_COMMIT(); }

        const __half* xs = smh + s * QKV_STAGE_H;
        const __half* ws = xs + 128 * QKV_LDH;
        #pragma unroll
        for (int kk = 0; kk < 4; kk++) {
            wmma::fragment<wmma::matrix_a, 16, 16, 16, __half, wmma::row_major> af[2];
            #pragma unroll
            for (int mt = 0; mt < 2; mt++)
                wmma::load_matrix_sync(af[mt], xs + (msub + mt * 16) * QKV_LDH + kk * 16, QKV_LDH);
            #pragma unroll
            for (int mat = 0; mat < 3; mat++) {
                wmma::fragment<wmma::matrix_b, 16, 16, 16, __half, wmma::col_major> bf[2];
                #pragma unroll
                for (int nt = 0; nt < 2; nt++)
                    wmma::load_matrix_sync(bf[nt], ws + mat * (64 * QKV_LDH) + (nsub + nt * 16) * QKV_LDH + kk * 16, QKV_LDH);
                #pragma unroll
                for (int mt = 0; mt < 2; mt++)
                    #pragma unroll
                    for (int nt = 0; nt < 2; nt++)
                        wmma::mma_sync(acc[mat][mt][nt], af[mt], bf[nt], acc[mat][mt][nt]);
            }
        }
        if (ch < 7) CP_WAIT0();
        __syncthreads();
    }

    // ---- epilogue: stage each matrix through fp32 smem (ld 72), convert ----
    const int er = tid >> 1;                    // row 0..127
    const int eh = (tid & 1) * 32;              // col half 0/32
    float kwreg[32];

    #pragma unroll
    for (int mat = 0; mat < 3; mat++) {
        #pragma unroll
        for (int mt = 0; mt < 2; mt++)
            #pragma unroll
            for (int nt = 0; nt < 2; nt++)
                wmma::store_matrix_sync(smf + (size_t)(msub + mt * 16) * 72 + nsub + nt * 16,
                                        acc[mat][mt][nt], 72, wmma::mem_row_major);
        __syncthreads();

        const float* src = smf + er * 72 + eh;
        size_t gbase = (size_t)(m0 + er) * DIM + n0 + eh;
        if (mat == 0) {           // sigmoid(q) -> fp32
            #pragma unroll
            for (int q = 0; q < 8; q++) {
                float4 v = *(const float4*)(src + q * 4);
                float4 o;
                o.x = 1.0f / (1.0f + __expf(-v.x));
                o.y = 1.0f / (1.0f + __expf(-v.y));
                o.z = 1.0f / (1.0f + __expf(-v.z));
                o.w = 1.0f / (1.0f + __expf(-v.w));
                *(float4*)(g_sq + gbase + q * 4) = o;
            }
        } else if (mat == 1) {    // exp(k) -> fp16, stash fp32
            #pragma unroll
            for (int q = 0; q < 8; q++) {
                float4 v = *(const float4*)(src + q * 4);
                float4 e;
                e.x = __expf(v.x); e.y = __expf(v.y);
                e.z = __expf(v.z); e.w = __expf(v.w);
                kwreg[q * 4 + 0] = e.x; kwreg[q * 4 + 1] = e.y;
                kwreg[q * 4 + 2] = e.z; kwreg[q * 4 + 3] = e.w;
                __half2* dst = (__half2*)(g_kwh + gbase + q * 4);
                dst[0] = __floats2half2_rn(e.x, e.y);
                dst[1] = __floats2half2_rn(e.z, e.w);
            }
        } else {                  // exp(k)*v -> fp16
            #pragma unroll
            for (int q = 0; q < 8; q++) {
                float4 v = *(const float4*)(src + q * 4);
                __half2* dst = (__half2*)(g_kvh + gbase + q * 4);
                dst[0] = __floats2half2_rn(kwreg[q * 4 + 0] * v.x, kwreg[q * 4 + 1] * v.y);
                dst[1] = __floats2half2_rn(kwreg[q * 4 + 2] * v.z, kwreg[q * 4 + 3] * v.w);
            }
        }
        __syncthreads();
    }
}

// ============================================================================
// Kernel 2: WMMA fp16 dual aggregation GEMM.
//   CTA 128d x 64j, 256 thr = 8 warps (4m x 2n), warp 32x32, fp32 acc.
//   2 CTAs/SM (regs) -> grid 1024, per-SM quantum ~7 => ~1% tail.
//   BK=64 (4 x k16), 32 chunks, 32 barriers.
//   A (kv/kw) ld 168 halves; dw (exp(c*dis)) ld 72 halves; both conflict-free.
// ============================================================================
#define AGG_LDH   168                          // kv/kw tile ld (128 d + pad)
#define AGG_DWLD  72                           // dw tile ld (64 j + pad)
#define AGG_A_H   (64 * AGG_LDH)               // 10752 halves per tensor
#define AGG_STAGE_H (2 * AGG_A_H + 64 * AGG_DWLD)  // 26112 halves (52224 B)
#define AGG_EPI_LD 136
#define AGG_SMEM_EPI (64 * AGG_EPI_LD * 4)     // 34816 B
#define AGG_SMEM (2 * AGG_STAGE_H * 2)         // 104448 B (>= epilogue)

__global__ __launch_bounds__(256, 2)
void agg_wmma(const float* __restrict__ dis,
              const float* __restrict__ alpha_p,
              float* __restrict__ out)
{
    extern __shared__ char smraw[];
    __half* smh = (__half*)smraw;
    float*  smf = (float*)smraw;
    const int tid = threadIdx.x;
    const int wid = tid >> 5;
    const int b   = blockIdx.z;
    const int j0  = blockIdx.y * 64;
    const int d0  = blockIdx.x * 128;
    const float c = -alpha_p[0] * 11.0f;       // -alpha * log2(2048)
    const int wm = wid & 3, wn = wid >> 2;     // 4m x 2n
    const int msub = wm * 32, nsub = wn * 32;
    const uint32_t sb = smem_u32(smraw);

    wmma::fragment<wmma::accumulator, 16, 16, 16, float> acc1[2][2], acc2[2][2];
    #pragma unroll
    for (int mt = 0; mt < 2; mt++)
        #pragma unroll
        for (int nt = 0; nt < 2; nt++) {
            wmma::fill_fragment(acc1[mt][nt], 0.0f);
            wmma::fill_fragment(acc2[mt][nt], 0.0f);
        }

    const __half* kvb  = g_kvh + (size_t)b * SEQ * DIM;
    const __half* kwb  = g_kwh + (size_t)b * SEQ * DIM;
    const float*  disb = dis   + (size_t)b * SEQ * SEQ;

    // kv/kw tiles: 64 i x 128 d halves (16 chunks/row, 1024 chunks/tensor)
    auto issue = [&](int s, int i0) {
        uint32_t st = sb + s * (AGG_STAGE_H * 2);
        #pragma unroll
        for (int j = 0; j < 4; j++) {
            int id = tid + j * 256;
            int i = id >> 4, seg = id & 15;
            CP16(st + i * (AGG_LDH * 2) + seg * 16,
                 kvb + (size_t)(i0 + i) * DIM + d0 + seg * 8);
            CP16(st + AGG_A_H * 2 + i * (AGG_LDH * 2) + seg * 16,
                 kwb + (size_t)(i0 + i) * DIM + d0 + seg * 8);
        }
    };
    // dis tile: 64 i x 64 j fp32 (LDG -> exp -> fp16 STS), 4 f4 per thread
    float4 dv[4];
    auto ldg_dis = [&](int i0) {
        #pragma unroll
        for (int p = 0; p < 4; p++) {
            int i = (tid >> 4) + p * 16;
            int q = (tid & 15) * 4;
            dv[p] = *(const float4*)(disb + (size_t)(i0 + i) * SEQ + j0 + q);
        }
    };
    auto sts_dis = [&](int s) {
        __half* dw = smh + s * AGG_STAGE_H + 2 * AGG_A_H;
        #pragma unroll
        for (int p = 0; p < 4; p++) {
            int i = (tid >> 4) + p * 16;
            int q = (tid & 15) * 4;
            __half2* d2 = (__half2*)(dw + i * AGG_DWLD + q);
            d2[0] = __floats2half2_rn(__expf(c * dv[p].x), __expf(c * dv[p].y));
            d2[1] = __floats2half2_rn(__expf(c * dv[p].z), __expf(c * dv[p].w));
        }
    };

    issue(0, 0); CP_COMMIT();
    ldg_dis(0); sts_dis(0);
    CP_WAIT0();
    __syncthreads();

    for (int ch = 0; ch < 32; ch++) {
        const int s = ch & 1;
        if (ch < 31) { issue(s ^ 1, (ch + 1) * 64); CP_COMMIT(); ldg_dis((ch + 1) * 64); }

        const __half* st   = smh + s * AGG_STAGE_H;
        const __half* kwst = st + AGG_A_H;
        const __half* dwst = st + 2 * AGG_A_H;
        #pragma unroll
        for (int kk = 0; kk < 4; kk++) {
            wmma::fragment<wmma::matrix_a, 16, 16, 16, __half, wmma::col_major> a1[2], a2[2];
            wmma::fragment<wmma::matrix_b, 16, 16, 16, __half, wmma::row_major> bf[2];
            #pragma unroll
            for (int mt = 0; mt < 2; mt++) {
                wmma::load_matrix_sync(a1[mt], st   + (size_t)(kk * 16) * AGG_LDH + msub + mt * 16, AGG_LDH);
                wmma::load_matrix_sync(a2[mt], kwst + (size_t)(kk * 16) * AGG_LDH + msub + mt * 16, AGG_LDH);
            }
            #pragma unroll
            for (int nt = 0; nt < 2; nt++)
                wmma::load_matrix_sync(bf[nt], dwst + (size_t)(kk * 16) * AGG_DWLD + nsub + nt * 16, AGG_DWLD);
            #pragma unroll
            for (int mt = 0; mt < 2; mt++)
                #pragma unroll
                for (int nt = 0; nt < 2; nt++) {
                    wmma::mma_sync(acc1[mt][nt], a1[mt], bf[nt], acc1[mt][nt]);
                    wmma::mma_sync(acc2[mt][nt], a2[mt], bf[nt], acc2[mt][nt]);
                }
        }

        if (ch < 31) { sts_dis(s ^ 1); CP_WAIT0(); }
        __syncthreads();
    }

    // ----- epilogue: ratio in-fragment, transpose via mem_col_major -> smem -
    #pragma unroll
    for (int mt = 0; mt < 2; mt++)
        #pragma unroll
        for (int nt = 0; nt < 2; nt++) {
            #pragma unroll
            for (int e = 0; e < acc1[mt][nt].num_elements; e++)
                acc1[mt][nt].x[e] = __fdividef(acc1[mt][nt].x[e], acc2[mt][nt].x[e]);
            wmma::store_matrix_sync(smf + (size_t)(nsub + nt * 16) * AGG_EPI_LD + msub + mt * 16,
                                    acc1[mt][nt], AGG_EPI_LD, wmma::mem_col_major);
        }
    __syncthreads();

    {
        const int j   = tid >> 2;                 // 0..63
        const int seg = (tid & 3) * 32;
        const float* ser = smf + j * AGG_EPI_LD + seg;
        const float* sqr = g_sq + ((size_t)b * SEQ + j0 + j) * DIM + d0 + seg;
        float*      outr = out  + ((size_t)b * SEQ + j0 + j) * DIM + d0 + seg;
        #pragma unroll
        for (int q = 0; q < 8; q++) {
            float4 rv = *(const float4*)(ser + q * 4);
            float4 sv = *(const float4*)(sqr + q * 4);
            float4 o;
            o.x = sv.x * rv.x; o.y = sv.y * rv.y;
            o.z = sv.z * rv.z; o.w = sv.w * rv.w;
            *(float4*)(outr + q * 4) = o;
        }
    }
}

// ============================================================================
extern "C" void kernel_launch(void* const* d_in, const int* in_sizes, int n_in,
                              void* d_out, int out_size)
{
    const float* x     = (const float*)d_in[0];
    const float* dis   = (const float*)d_in[1];
    const float* Wq    = (const float*)d_in[2];
    const float* Wk    = (const float*)d_in[3];
    const float* Wv    = (const float*)d_in[4];
    const float* alpha = (const float*)d_in[5];
    float* out = (float*)d_out;

    cudaFuncSetAttribute(qkv_wmma, cudaFuncAttributeMaxDynamicSharedMemorySize, QKV_SMEM);
    cudaFuncSetAttribute(agg_wmma, cudaFuncAttributeMaxDynamicSharedMemorySize, AGG_SMEM);

    prep_half<<<(2097152 + 196608 + 255) / 256, 256>>>(x, Wq, Wk, Wv);

    dim3 g1(DIM / 64, (BATCH * SEQ) / 128);   // (8, 128)
    qkv_wmma<<<g1, 256, QKV_SMEM>>>();

    dim3 g2(DIM / 128, SEQ / 64, BATCH);      // (4, 32, 8) = 1024 CTAs
    agg_wmma<<<g2, 256, AGG_SMEM>>>(dis, alpha, out);
}